// round 10
// baseline (speedup 1.0000x reference)
#include <cuda_runtime.h>
#include <cuda_fp16.h>
#include <math.h>

#define NN   10000
#define EIN  320000
#define ETOT 330000
#define MAXD 1024

// ---------------- device scratch ----------------
__device__ __half g_x16[NN * 256];
__device__ __half g_w1[256 * 512];
__device__ __half g_w2[512 * 512];
__device__ __half g_w3[512 * 64 + 256];   // zero pad for OOB-column tile reads
__device__ __half g_h16[NN * 512];
__device__ __half g_o16[NN * 512];
__device__ float  g_als[NN * 4];
__device__ float  g_ald[NN * 4];
__device__ int    g_rowptr[NN + 1];
__device__ int    g_cnt[NN];
__device__ int    g_srcs[ETOT];

__device__ __forceinline__ int edge_src(const int* ei, int e) {
    return (e < EIN) ? ei[e] : (e - EIN);
}
__device__ __forceinline__ int edge_dst(const int* ei, int e) {
    return (e < EIN) ? ei[EIN + e] : (e - EIN);
}

// ---------------- fused prep: zero cnt + all fp32->fp16 conversions ----------------
__device__ __forceinline__ void cvt4(const float* in, __half* out, int i) {
    float4 v = *(const float4*)&in[i * 4];
    *(__half2*)&out[i * 4]     = __floats2half2_rn(v.x, v.y);
    *(__half2*)&out[i * 4 + 2] = __floats2half2_rn(v.z, v.w);
}

#define NX4  (NN * 256 / 4)
#define NW14 (256 * 512 / 4)
#define NW24 (512 * 512 / 4)
#define NW34 (512 * 64 / 4)

__global__ void k_prep(const float* __restrict__ x, const float* __restrict__ W1,
                       const float* __restrict__ W2, const float* __restrict__ W3)
{
    int i = blockIdx.x * blockDim.x + threadIdx.x;
    if (i < NN) g_cnt[i] = 0;
    if (i < NX4) { cvt4(x, g_x16, i); return; }
    int j = i - NX4;
    if (j < NW14) { cvt4(W1, g_w1, j); return; }
    j -= NW14;
    if (j < NW24) { cvt4(W2, g_w2, j); return; }
    j -= NW24;
    if (j < NW34) { cvt4(W3, g_w3, j); return; }
}

// ---------------- CSR build ----------------
__global__ void k_zero_cnt() {
    int i = blockIdx.x * blockDim.x + threadIdx.x;
    if (i < NN) g_cnt[i] = 0;
}

__global__ void k_count(const int* __restrict__ ei) {
    int e = blockIdx.x * blockDim.x + threadIdx.x;
    if (e < ETOT) atomicAdd(&g_cnt[edge_dst(ei, e)], 1);
}

__global__ void k_scan() {
    __shared__ int warp_sums[32];
    __shared__ int carry_sh;
    int t = threadIdx.x, lane = t & 31, w = t >> 5;
    if (t == 0) { carry_sh = 0; g_rowptr[0] = 0; }
    __syncthreads();
    for (int base = 0; base < NN; base += 1024) {
        int v = (base + t < NN) ? g_cnt[base + t] : 0;
        int s = v;
#pragma unroll
        for (int off = 1; off < 32; off <<= 1) {
            int x = __shfl_up_sync(0xffffffffu, s, off);
            if (lane >= off) s += x;
        }
        if (lane == 31) warp_sums[w] = s;
        __syncthreads();
        if (w == 0) {
            int ws = warp_sums[lane];
#pragma unroll
            for (int off = 1; off < 32; off <<= 1) {
                int x = __shfl_up_sync(0xffffffffu, ws, off);
                if (lane >= off) ws += x;
            }
            warp_sums[lane] = ws;
        }
        __syncthreads();
        int incl = s + ((w > 0) ? warp_sums[w - 1] : 0) + carry_sh;
        if (base + t < NN) g_rowptr[base + t + 1] = incl;
        __syncthreads();
        if (t == 1023) carry_sh = incl;
        __syncthreads();
    }
}

__global__ void k_scatter(const int* __restrict__ ei) {
    int e = blockIdx.x * blockDim.x + threadIdx.x;
    if (e < ETOT) {
        int d = edge_dst(ei, e);
        int p = atomicAdd(&g_cnt[d], 1);
        g_srcs[g_rowptr[d] + p] = edge_src(ei, e);
    }
}

// ---------------- cp.async helpers ----------------
#define CP16(smem_u32, gptr) \
    asm volatile("cp.async.cg.shared.global [%0], [%1], 16;" :: "r"(smem_u32), "l"(gptr))
#define CP_COMMIT() asm volatile("cp.async.commit_group;")

// ---------------- GEMM 128x128, fused per-head attention-logit epilogue ----------------
// Block column == one head (C<=128). Computes C tile (fp16) AND
// g_als/g_ald[row*Hn + head] from fp32 accumulators.
__global__ __launch_bounds__(256) void gemm_f16(
    const __half* __restrict__ A, const __half* __restrict__ B,
    __half* __restrict__ C, int M, int N, int K,
    const float* __restrict__ a_src, const float* __restrict__ a_dst,
    int Hn, int Cn)
{
    __shared__ __align__(16) __half As[2][128][40];
    __shared__ __align__(16) __half Bs[2][32][136];
    __shared__ float asrc_sh[128], adst_sh[128];
    __shared__ float ps1[128][4], ps2[128][4];

    const int tid  = threadIdx.x;
    const int warp = tid >> 5, lane = tid & 31;
    const int warpM = warp >> 2, warpN = warp & 3;
    const int bm = blockIdx.y * 128, bn = blockIdx.x * 128;
    const int head = blockIdx.x;
    const int gid = lane >> 2, tig = lane & 3;

    // attention vectors for this head (zero-pad beyond Cn)
    if (tid < 128) {
        asrc_sh[tid] = (tid < Cn) ? a_src[head * Cn + tid] : 0.f;
        adst_sh[tid] = (tid < Cn) ? a_dst[head * Cn + tid] : 0.f;
    }

    float c[4][4][4];
#pragma unroll
    for (int mt = 0; mt < 4; mt++)
#pragma unroll
        for (int nt = 0; nt < 4; nt++)
#pragma unroll
            for (int r = 0; r < 4; r++) c[mt][nt][r] = 0.f;

    const int ntiles = K >> 5;
    const int ach0 = tid * 2, ach1 = tid * 2 + 1;

#define ISSUE_TILE(stage, k0)                                                     \
    {                                                                             \
        int _ar0 = ach0 >> 2, _ac0 = (ach0 & 3) * 8;                              \
        int _ar1 = ach1 >> 2, _ac1 = (ach1 & 3) * 8;                              \
        if (bm + _ar0 < M) {                                                      \
            unsigned _s = (unsigned)__cvta_generic_to_shared(&As[stage][_ar0][_ac0]); \
            CP16(_s, &A[(size_t)(bm + _ar0) * K + (k0) + _ac0]);                  \
        }                                                                         \
        if (bm + _ar1 < M) {                                                      \
            unsigned _s = (unsigned)__cvta_generic_to_shared(&As[stage][_ar1][_ac1]); \
            CP16(_s, &A[(size_t)(bm + _ar1) * K + (k0) + _ac1]);                  \
        }                                                                         \
        int _br0 = ach0 >> 4, _bc0 = (ach0 & 15) * 8;                             \
        int _br1 = ach1 >> 4, _bc1 = (ach1 & 15) * 8;                             \
        {                                                                         \
            unsigned _s = (unsigned)__cvta_generic_to_shared(&Bs[stage][_br0][_bc0]); \
            CP16(_s, &B[(size_t)((k0) + _br0) * N + bn + _bc0]);                  \
            _s = (unsigned)__cvta_generic_to_shared(&Bs[stage][_br1][_bc1]);      \
            CP16(_s, &B[(size_t)((k0) + _br1) * N + bn + _bc1]);                  \
        }                                                                         \
        CP_COMMIT();                                                              \
    }

    ISSUE_TILE(0, 0);
    if (ntiles > 1) ISSUE_TILE(1, 32);

    for (int kt = 0; kt < ntiles; kt++) {
        if (kt + 1 < ntiles)
            asm volatile("cp.async.wait_group 1;");
        else
            asm volatile("cp.async.wait_group 0;");
        __syncthreads();

        const int s = kt & 1;
#pragma unroll
        for (int ks = 0; ks < 2; ks++) {
            const int kb = ks * 16;
            unsigned a[4][4], b[4][2];
#pragma unroll
            for (int mt = 0; mt < 4; mt++) {
                int m  = warpM * 64 + mt * 16 + (lane & 15);
                int kc = kb + 8 * (lane >> 4);
                unsigned addr = (unsigned)__cvta_generic_to_shared(&As[s][m][kc]);
                asm volatile(
                    "ldmatrix.sync.aligned.m8n8.x4.shared.b16 {%0,%1,%2,%3}, [%4];"
                    : "=r"(a[mt][0]), "=r"(a[mt][1]), "=r"(a[mt][2]), "=r"(a[mt][3])
                    : "r"(addr));
            }
#pragma unroll
            for (int np = 0; np < 2; np++) {
                int kr = kb + (lane & 15);
                int nc = warpN * 32 + np * 16 + 8 * (lane >> 4);
                unsigned addr = (unsigned)__cvta_generic_to_shared(&Bs[s][kr][nc]);
                unsigned r0, r1, r2, r3;
                asm volatile(
                    "ldmatrix.sync.aligned.m8n8.x4.trans.shared.b16 {%0,%1,%2,%3}, [%4];"
                    : "=r"(r0), "=r"(r1), "=r"(r2), "=r"(r3)
                    : "r"(addr));
                b[np * 2][0]     = r0;
                b[np * 2][1]     = r1;
                b[np * 2 + 1][0] = r2;
                b[np * 2 + 1][1] = r3;
            }
#pragma unroll
            for (int mt = 0; mt < 4; mt++)
#pragma unroll
                for (int nt = 0; nt < 4; nt++) {
                    asm volatile(
                        "mma.sync.aligned.m16n8k16.row.col.f32.f16.f16.f32 "
                        "{%0,%1,%2,%3}, {%4,%5,%6,%7}, {%8,%9}, {%0,%1,%2,%3};"
                        : "+f"(c[mt][nt][0]), "+f"(c[mt][nt][1]),
                          "+f"(c[mt][nt][2]), "+f"(c[mt][nt][3])
                        : "r"(a[mt][0]), "r"(a[mt][1]), "r"(a[mt][2]), "r"(a[mt][3]),
                          "r"(b[nt][0]), "r"(b[nt][1]));
                }
        }
        __syncthreads();
        if (kt + 2 < ntiles) ISSUE_TILE(kt & 1, (kt + 2) * 32);
    }

    // --- store C + per-row attention dots from fp32 accumulators ---
#pragma unroll
    for (int mt = 0; mt < 4; mt++) {
        int row0 = bm + warpM * 64 + mt * 16 + gid;
        float s1a = 0.f, s2a = 0.f, s1b = 0.f, s2b = 0.f;
#pragma unroll
        for (int nt = 0; nt < 4; nt++) {
            int cl = warpN * 32 + nt * 8 + tig * 2;
            int col = bn + cl;
            if (col < N) {
                if (row0 < M)
                    *(__half2*)&C[(size_t)row0 * N + col] =
                        __floats2half2_rn(c[mt][nt][0], c[mt][nt][1]);
                if (row0 + 8 < M)
                    *(__half2*)&C[(size_t)(row0 + 8) * N + col] =
                        __floats2half2_rn(c[mt][nt][2], c[mt][nt][3]);
            }
            float w0 = asrc_sh[cl], w1 = asrc_sh[cl + 1];
            float d0 = adst_sh[cl], d1 = adst_sh[cl + 1];
            s1a += c[mt][nt][0] * w0 + c[mt][nt][1] * w1;
            s2a += c[mt][nt][0] * d0 + c[mt][nt][1] * d1;
            s1b += c[mt][nt][2] * w0 + c[mt][nt][3] * w1;
            s2b += c[mt][nt][2] * d0 + c[mt][nt][3] * d1;
        }
#pragma unroll
        for (int off = 1; off < 4; off <<= 1) {
            s1a += __shfl_xor_sync(0xffffffffu, s1a, off);
            s2a += __shfl_xor_sync(0xffffffffu, s2a, off);
            s1b += __shfl_xor_sync(0xffffffffu, s1b, off);
            s2b += __shfl_xor_sync(0xffffffffu, s2b, off);
        }
        if (tig == 0) {
            int rl = warpM * 64 + mt * 16 + gid;
            ps1[rl][warpN] = s1a;     ps2[rl][warpN] = s2a;
            ps1[rl + 8][warpN] = s1b; ps2[rl + 8][warpN] = s2b;
        }
    }
    __syncthreads();
    if (tid < 128) {
        int row = bm + tid;
        if (row < M) {
            g_als[row * Hn + head] =
                ps1[tid][0] + ps1[tid][1] + ps1[tid][2] + ps1[tid][3];
            g_ald[row * Hn + head] =
                ps2[tid][0] + ps2[tid][1] + ps2[tid][2] + ps2[tid][3];
        }
    }
}

// ---------------- fused softmax + aggregation ----------------
template <int H, int C, bool F16OUT>
__global__ void gat_agg(const __half* __restrict__ feat,
                        const float* __restrict__ bias,
                        float* __restrict__ outf,
                        __half* __restrict__ outh,
                        int apply_elu)
{
    constexpr int HCv = H * C;
    constexpr int BT = HCv / 2;
    int n = blockIdx.x;
    int t = threadIdx.x;
    int warp = t >> 5, lane = t & 31;

    int start = g_rowptr[n];
    int deg = g_rowptr[n + 1] - start;

    __shared__ float e_sh[MAXD * H];
    __shared__ int   src_sh[MAXD];
    __shared__ float m_run[H], d_run[H], f_sh[H];

    if (t < H) { m_run[t] = -1e30f; d_run[t] = 0.f; }

    float aldv[H];
#pragma unroll
    for (int hh = 0; hh < H; hh++) aldv[hh] = g_ald[n * H + hh];

    const int hd = (2 * t) / C;
    float2 acc = make_float2(0.f, 0.f);
    const __half2* feat2 = (const __half2*)feat;

    for (int w0 = 0; w0 < deg; w0 += MAXD) {
        int wn = min(MAXD, deg - w0);
        __syncthreads();

        for (int i = t; i < wn; i += BT) {
            int s = g_srcs[start + w0 + i];
            src_sh[i] = s;
            if (H == 4) {
                float4 av = *(const float4*)&g_als[s * 4];
                float e0 = av.x + aldv[0], e1 = av.y + aldv[1];
                float e2 = av.z + aldv[2], e3 = av.w + aldv[3];
                e_sh[i * 4 + 0] = (e0 > 0.f) ? e0 : 0.2f * e0;
                e_sh[i * 4 + 1] = (e1 > 0.f) ? e1 : 0.2f * e1;
                e_sh[i * 4 + 2] = (e2 > 0.f) ? e2 : 0.2f * e2;
                e_sh[i * 4 + 3] = (e3 > 0.f) ? e3 : 0.2f * e3;
            } else {
                float e0 = g_als[s] + aldv[0];
                e_sh[i] = (e0 > 0.f) ? e0 : 0.2f * e0;
            }
        }
        __syncthreads();

        if (warp < H) {
            float wm = -1e30f;
            for (int j = lane; j < wn; j += 32)
                wm = fmaxf(wm, e_sh[j * H + warp]);
#pragma unroll
            for (int off = 16; off; off >>= 1)
                wm = fmaxf(wm, __shfl_xor_sync(0xffffffffu, wm, off));
            float nm = fmaxf(m_run[warp], wm);
            float s = 0.f;
            for (int j = lane; j < wn; j += 32)
                s += __expf(e_sh[j * H + warp] - nm);
#pragma unroll
            for (int off = 16; off; off >>= 1)
                s += __shfl_xor_sync(0xffffffffu, s, off);
            if (lane == 0) {
                float f = __expf(m_run[warp] - nm);
                f_sh[warp] = f;
                d_run[warp] = d_run[warp] * f + s;
                m_run[warp] = nm;
            }
        }
        __syncthreads();

        for (int i = t; i < wn * H; i += BT) {
            int hh = i & (H - 1);
            e_sh[i] = __expf(e_sh[i] - m_run[hh]);
        }
        acc.x *= f_sh[hd];
        acc.y *= f_sh[hd];
        __syncthreads();

        int j = 0;
        for (; j + 4 <= wn; j += 4) {
#pragma unroll
            for (int u = 0; u < 4; u++) {
                float w = e_sh[(j + u) * H + hd];
                float2 f = __half22float2(feat2[(size_t)src_sh[j + u] * (HCv / 2) + t]);
                acc.x += w * f.x;
                acc.y += w * f.y;
            }
        }
        for (; j < wn; j++) {
            float w = e_sh[j * H + hd];
            float2 f = __half22float2(feat2[(size_t)src_sh[j] * (HCv / 2) + t]);
            acc.x += w * f.x;
            acc.y += w * f.y;
        }
    }

    float inv = 1.f / d_run[hd];
    float v0 = acc.x * inv + bias[2 * t];
    float v1 = acc.y * inv + bias[2 * t + 1];
    if (apply_elu) {
        v0 = (v0 > 0.f) ? v0 : (__expf(v0) - 1.f);
        v1 = (v1 > 0.f) ? v1 : (__expf(v1) - 1.f);
    }
    if (F16OUT)
        *(__half2*)&outh[(size_t)n * HCv + 2 * t] = __floats2half2_rn(v0, v1);
    else
        *(float2*)&outf[(size_t)n * HCv + 2 * t] = make_float2(v0, v1);
}

// ---------------- launch ----------------
extern "C" void kernel_launch(void* const* d_in, const int* in_sizes, int n_in,
                              void* d_out, int out_size)
{
    const float* x   = (const float*)d_in[0];
    const int*   ei  = (const int*)d_in[1];
    const float* W1  = (const float*)d_in[2];
    const float* as1 = (const float*)d_in[3];
    const float* ad1 = (const float*)d_in[4];
    const float* b1  = (const float*)d_in[5];
    const float* W2  = (const float*)d_in[6];
    const float* as2 = (const float*)d_in[7];
    const float* ad2 = (const float*)d_in[8];
    const float* b2  = (const float*)d_in[9];
    const float* W3  = (const float*)d_in[10];
    const float* as3 = (const float*)d_in[11];
    const float* ad3 = (const float*)d_in[12];
    const float* b3  = (const float*)d_in[13];
    float* out = (float*)d_out;

    __half *x16, *w1, *w2, *w3, *h16, *o16;
    cudaGetSymbolAddress((void**)&x16, g_x16);
    cudaGetSymbolAddress((void**)&w1, g_w1);
    cudaGetSymbolAddress((void**)&w2, g_w2);
    cudaGetSymbolAddress((void**)&w3, g_w3);
    cudaGetSymbolAddress((void**)&h16, g_h16);
    cudaGetSymbolAddress((void**)&o16, g_o16);

    // --- prep + CSR build ---
    int prep_threads = NX4 + NW14 + NW24 + NW34;
    k_prep<<<(prep_threads + 255) / 256, 256>>>(x, W1, W2, W3);
    k_count<<<(ETOT + 255) / 256, 256>>>(ei);
    k_scan<<<1, 1024>>>();
    k_zero_cnt<<<(NN + 255) / 256, 256>>>();
    k_scatter<<<(ETOT + 255) / 256, 256>>>(ei);

    dim3 g12(4, (NN + 127) / 128);
    dim3 g3(1, (NN + 127) / 128);

    // --- layer 1 ---
    gemm_f16<<<g12, 256>>>(x16, w1, h16, NN, 512, 256, as1, ad1, 4, 128);
    gat_agg<4, 128, true><<<NN, 256>>>(h16, b1, nullptr, o16, 1);

    // --- layer 2 ---
    gemm_f16<<<g12, 256>>>(o16, w2, h16, NN, 512, 512, as2, ad2, 4, 128);
    gat_agg<4, 128, true><<<NN, 256>>>(h16, b2, nullptr, o16, 1);

    // --- layer 3 ---
    gemm_f16<<<g3, 256>>>(o16, w3, h16, NN, 64, 512, as3, ad3, 1, 64);
    gat_agg<1, 64, false><<<NN, 32>>>(h16, b3, out, nullptr, 0);
}

// round 11
// speedup vs baseline: 1.4327x; 1.4327x over previous
#include <cuda_runtime.h>
#include <cuda_fp16.h>
#include <math.h>

#define NN   10000
#define EIN  320000
#define ETOT 330000
#define MAXD 1024

// ---------------- device scratch ----------------
__device__ __half g_x16[NN * 256];
__device__ __half g_w1[256 * 512];
__device__ __half g_w2[512 * 512];
__device__ __half g_w3[512 * 64 + 256];
__device__ __half g_h16[NN * 512];
__device__ __half g_o16[NN * 512];
__device__ float  g_als[NN * 4];
__device__ float  g_ald[NN * 4];
__device__ int    g_rowptr[NN + 1];
__device__ int    g_cnt[NN];
__device__ int    g_srcs[ETOT];

__device__ __forceinline__ int edge_src(const int* ei, int e) {
    return (e < EIN) ? ei[e] : (e - EIN);
}
__device__ __forceinline__ int edge_dst(const int* ei, int e) {
    return (e < EIN) ? ei[EIN + e] : (e - EIN);
}

// ---------------- fused prep: zero cnt + all fp32->fp16 conversions ----------------
__device__ __forceinline__ void cvt4(const float* in, __half* out, int i) {
    float4 v = *(const float4*)&in[i * 4];
    *(__half2*)&out[i * 4]     = __floats2half2_rn(v.x, v.y);
    *(__half2*)&out[i * 4 + 2] = __floats2half2_rn(v.z, v.w);
}

#define NX4  (NN * 256 / 4)
#define NW14 (256 * 512 / 4)
#define NW24 (512 * 512 / 4)
#define NW34 (512 * 64 / 4)

__global__ void k_prep(const float* __restrict__ x, const float* __restrict__ W1,
                       const float* __restrict__ W2, const float* __restrict__ W3)
{
    int i = blockIdx.x * blockDim.x + threadIdx.x;
    if (i < NN) g_cnt[i] = 0;
    if (i < NX4) { cvt4(x, g_x16, i); return; }
    int j = i - NX4;
    if (j < NW14) { cvt4(W1, g_w1, j); return; }
    j -= NW14;
    if (j < NW24) { cvt4(W2, g_w2, j); return; }
    j -= NW24;
    if (j < NW34) { cvt4(W3, g_w3, j); return; }
}

// ---------------- CSR build ----------------
__global__ void k_zero_cnt() {
    int i = blockIdx.x * blockDim.x + threadIdx.x;
    if (i < NN) g_cnt[i] = 0;
}

__global__ void k_count(const int* __restrict__ ei) {
    int e = blockIdx.x * blockDim.x + threadIdx.x;
    if (e < ETOT) atomicAdd(&g_cnt[edge_dst(ei, e)], 1);
}

__global__ void k_scan() {
    __shared__ int warp_sums[32];
    __shared__ int carry_sh;
    int t = threadIdx.x, lane = t & 31, w = t >> 5;
    if (t == 0) { carry_sh = 0; g_rowptr[0] = 0; }
    __syncthreads();
    for (int base = 0; base < NN; base += 1024) {
        int v = (base + t < NN) ? g_cnt[base + t] : 0;
        int s = v;
#pragma unroll
        for (int off = 1; off < 32; off <<= 1) {
            int x = __shfl_up_sync(0xffffffffu, s, off);
            if (lane >= off) s += x;
        }
        if (lane == 31) warp_sums[w] = s;
        __syncthreads();
        if (w == 0) {
            int ws = warp_sums[lane];
#pragma unroll
            for (int off = 1; off < 32; off <<= 1) {
                int x = __shfl_up_sync(0xffffffffu, ws, off);
                if (lane >= off) ws += x;
            }
            warp_sums[lane] = ws;
        }
        __syncthreads();
        int incl = s + ((w > 0) ? warp_sums[w - 1] : 0) + carry_sh;
        if (base + t < NN) g_rowptr[base + t + 1] = incl;
        __syncthreads();
        if (t == 1023) carry_sh = incl;
        __syncthreads();
    }
}

__global__ void k_scatter(const int* __restrict__ ei) {
    int e = blockIdx.x * blockDim.x + threadIdx.x;
    if (e < ETOT) {
        int d = edge_dst(ei, e);
        int p = atomicAdd(&g_cnt[d], 1);
        g_srcs[g_rowptr[d] + p] = edge_src(ei, e);
    }
}

// ---------------- cp.async helpers ----------------
#define CP16(smem_u32, gptr) \
    asm volatile("cp.async.cg.shared.global [%0], [%1], 16;" :: "r"(smem_u32), "l"(gptr))
#define CP_COMMIT() asm volatile("cp.async.commit_group;")

// ---------------- FP16 GEMM: 3-stage cp.async pipeline, ldmatrix(.trans) ----------------
__global__ __launch_bounds__(256) void gemm_f16(
    const __half* __restrict__ A, const __half* __restrict__ B,
    __half* __restrict__ C, int M, int N, int K)
{
    __shared__ __align__(16) __half As[3][128][40];
    __shared__ __align__(16) __half Bs[3][32][136];

    const int tid  = threadIdx.x;
    const int warp = tid >> 5, lane = tid & 31;
    const int warpM = warp >> 2, warpN = warp & 3;
    const int bm = blockIdx.y * 128, bn = blockIdx.x * 128;
    const int gid = lane >> 2, tig = lane & 3;

    float c[4][4][4];
#pragma unroll
    for (int mt = 0; mt < 4; mt++)
#pragma unroll
        for (int nt = 0; nt < 4; nt++)
#pragma unroll
            for (int r = 0; r < 4; r++) c[mt][nt][r] = 0.f;

    const int ntiles = K >> 5;
    const int ach0 = tid * 2, ach1 = tid * 2 + 1;

#define ISSUE_TILE(stage, k0)                                                     \
    {                                                                             \
        int _ar0 = ach0 >> 2, _ac0 = (ach0 & 3) * 8;                              \
        int _ar1 = ach1 >> 2, _ac1 = (ach1 & 3) * 8;                              \
        if (bm + _ar0 < M) {                                                      \
            unsigned _s = (unsigned)__cvta_generic_to_shared(&As[stage][_ar0][_ac0]); \
            CP16(_s, &A[(size_t)(bm + _ar0) * K + (k0) + _ac0]);                  \
        }                                                                         \
        if (bm + _ar1 < M) {                                                      \
            unsigned _s = (unsigned)__cvta_generic_to_shared(&As[stage][_ar1][_ac1]); \
            CP16(_s, &A[(size_t)(bm + _ar1) * K + (k0) + _ac1]);                  \
        }                                                                         \
        int _br0 = ach0 >> 4, _bc0 = (ach0 & 15) * 8;                             \
        int _br1 = ach1 >> 4, _bc1 = (ach1 & 15) * 8;                             \
        {                                                                         \
            unsigned _s = (unsigned)__cvta_generic_to_shared(&Bs[stage][_br0][_bc0]); \
            CP16(_s, &B[(size_t)((k0) + _br0) * N + bn + _bc0]);                  \
            _s = (unsigned)__cvta_generic_to_shared(&Bs[stage][_br1][_bc1]);      \
            CP16(_s, &B[(size_t)((k0) + _br1) * N + bn + _bc1]);                  \
        }                                                                         \
        CP_COMMIT();                                                              \
    }

    ISSUE_TILE(0, 0);
    if (ntiles > 1) ISSUE_TILE(1, 32);
    if (ntiles > 2) ISSUE_TILE(2, 64);

    for (int kt = 0; kt < ntiles; kt++) {
        if (kt + 2 < ntiles)
            asm volatile("cp.async.wait_group 2;");
        else if (kt + 1 < ntiles)
            asm volatile("cp.async.wait_group 1;");
        else
            asm volatile("cp.async.wait_group 0;");
        __syncthreads();

        const int s = kt % 3;
#pragma unroll
        for (int ks = 0; ks < 2; ks++) {
            const int kb = ks * 16;
            unsigned a[4][4], b[4][2];
#pragma unroll
            for (int mt = 0; mt < 4; mt++) {
                int m  = warpM * 64 + mt * 16 + (lane & 15);
                int kc = kb + 8 * (lane >> 4);
                unsigned addr = (unsigned)__cvta_generic_to_shared(&As[s][m][kc]);
                asm volatile(
                    "ldmatrix.sync.aligned.m8n8.x4.shared.b16 {%0,%1,%2,%3}, [%4];"
                    : "=r"(a[mt][0]), "=r"(a[mt][1]), "=r"(a[mt][2]), "=r"(a[mt][3])
                    : "r"(addr));
            }
#pragma unroll
            for (int np = 0; np < 2; np++) {
                int kr = kb + (lane & 15);
                int nc = warpN * 32 + np * 16 + 8 * (lane >> 4);
                unsigned addr = (unsigned)__cvta_generic_to_shared(&Bs[s][kr][nc]);
                unsigned r0, r1, r2, r3;
                asm volatile(
                    "ldmatrix.sync.aligned.m8n8.x4.trans.shared.b16 {%0,%1,%2,%3}, [%4];"
                    : "=r"(r0), "=r"(r1), "=r"(r2), "=r"(r3)
                    : "r"(addr));
                b[np * 2][0]     = r0;
                b[np * 2][1]     = r1;
                b[np * 2 + 1][0] = r2;
                b[np * 2 + 1][1] = r3;
            }
#pragma unroll
            for (int mt = 0; mt < 4; mt++)
#pragma unroll
                for (int nt = 0; nt < 4; nt++) {
                    asm volatile(
                        "mma.sync.aligned.m16n8k16.row.col.f32.f16.f16.f32 "
                        "{%0,%1,%2,%3}, {%4,%5,%6,%7}, {%8,%9}, {%0,%1,%2,%3};"
                        : "+f"(c[mt][nt][0]), "+f"(c[mt][nt][1]),
                          "+f"(c[mt][nt][2]), "+f"(c[mt][nt][3])
                        : "r"(a[mt][0]), "r"(a[mt][1]), "r"(a[mt][2]), "r"(a[mt][3]),
                          "r"(b[nt][0]), "r"(b[nt][1]));
                }
        }
        __syncthreads();
        if (kt + 3 < ntiles) ISSUE_TILE(kt % 3, (kt + 3) * 32);
    }

#pragma unroll
    for (int mt = 0; mt < 4; mt++) {
        int row0 = bm + warpM * 64 + mt * 16 + gid;
#pragma unroll
        for (int nt = 0; nt < 4; nt++) {
            int col = bn + warpN * 32 + nt * 8 + tig * 2;
            if (col < N) {
                if (row0 < M)
                    *(__half2*)&C[(size_t)row0 * N + col] =
                        __floats2half2_rn(c[mt][nt][0], c[mt][nt][1]);
                if (row0 + 8 < M)
                    *(__half2*)&C[(size_t)(row0 + 8) * N + col] =
                        __floats2half2_rn(c[mt][nt][2], c[mt][nt][3]);
            }
        }
    }
}

// ---------------- per-node attention logits ----------------
__global__ void node_al(const __half* __restrict__ feat,
                        const float* __restrict__ a_src,
                        const float* __restrict__ a_dst,
                        int Hn, int Cn)
{
    int n = blockIdx.x;
    int w = threadIdx.x >> 5;
    int lane = threadIdx.x & 31;
    if (w >= Hn) return;
    const __half* row = feat + (size_t)n * Hn * Cn + w * Cn;
    float s1 = 0.f, s2 = 0.f;
    for (int c = lane; c < Cn; c += 32) {
        float v = __half2float(row[c]);
        s1 += v * a_src[w * Cn + c];
        s2 += v * a_dst[w * Cn + c];
    }
#pragma unroll
    for (int off = 16; off; off >>= 1) {
        s1 += __shfl_xor_sync(0xffffffffu, s1, off);
        s2 += __shfl_xor_sync(0xffffffffu, s2, off);
    }
    if (lane == 0) {
        g_als[n * Hn + w] = s1;
        g_ald[n * Hn + w] = s2;
    }
}

// ---------------- fused softmax + aggregation ----------------
template <int H, int C, bool F16OUT>
__global__ void gat_agg(const __half* __restrict__ feat,
                        const float* __restrict__ bias,
                        float* __restrict__ outf,
                        __half* __restrict__ outh,
                        int apply_elu)
{
    constexpr int HCv = H * C;
    constexpr int BT = HCv / 2;
    int n = blockIdx.x;
    int t = threadIdx.x;
    int warp = t >> 5, lane = t & 31;

    int start = g_rowptr[n];
    int deg = g_rowptr[n + 1] - start;

    __shared__ float e_sh[MAXD * H];
    __shared__ int   src_sh[MAXD];
    __shared__ float m_run[H], d_run[H], f_sh[H];

    if (t < H) { m_run[t] = -1e30f; d_run[t] = 0.f; }

    float aldv[H];
#pragma unroll
    for (int hh = 0; hh < H; hh++) aldv[hh] = g_ald[n * H + hh];

    const int hd = (2 * t) / C;
    float2 acc = make_float2(0.f, 0.f);
    const __half2* feat2 = (const __half2*)feat;

    for (int w0 = 0; w0 < deg; w0 += MAXD) {
        int wn = min(MAXD, deg - w0);
        __syncthreads();

        for (int i = t; i < wn; i += BT) {
            int s = g_srcs[start + w0 + i];
            src_sh[i] = s;
            if (H == 4) {
                float4 av = *(const float4*)&g_als[s * 4];
                float e0 = av.x + aldv[0], e1 = av.y + aldv[1];
                float e2 = av.z + aldv[2], e3 = av.w + aldv[3];
                e_sh[i * 4 + 0] = (e0 > 0.f) ? e0 : 0.2f * e0;
                e_sh[i * 4 + 1] = (e1 > 0.f) ? e1 : 0.2f * e1;
                e_sh[i * 4 + 2] = (e2 > 0.f) ? e2 : 0.2f * e2;
                e_sh[i * 4 + 3] = (e3 > 0.f) ? e3 : 0.2f * e3;
            } else {
                float e0 = g_als[s] + aldv[0];
                e_sh[i] = (e0 > 0.f) ? e0 : 0.2f * e0;
            }
        }
        __syncthreads();

        if (warp < H) {
            float wm = -1e30f;
            for (int j = lane; j < wn; j += 32)
                wm = fmaxf(wm, e_sh[j * H + warp]);
#pragma unroll
            for (int off = 16; off; off >>= 1)
                wm = fmaxf(wm, __shfl_xor_sync(0xffffffffu, wm, off));
            float nm = fmaxf(m_run[warp], wm);
            float s = 0.f;
            for (int j = lane; j < wn; j += 32)
                s += __expf(e_sh[j * H + warp] - nm);
#pragma unroll
            for (int off = 16; off; off >>= 1)
                s += __shfl_xor_sync(0xffffffffu, s, off);
            if (lane == 0) {
                float f = __expf(m_run[warp] - nm);
                f_sh[warp] = f;
                d_run[warp] = d_run[warp] * f + s;
                m_run[warp] = nm;
            }
        }
        __syncthreads();

        for (int i = t; i < wn * H; i += BT) {
            int hh = i & (H - 1);
            e_sh[i] = __expf(e_sh[i] - m_run[hh]);
        }
        acc.x *= f_sh[hd];
        acc.y *= f_sh[hd];
        __syncthreads();

        int j = 0;
        for (; j + 4 <= wn; j += 4) {
#pragma unroll
            for (int u = 0; u < 4; u++) {
                float w = e_sh[(j + u) * H + hd];
                float2 f = __half22float2(feat2[(size_t)src_sh[j + u] * (HCv / 2) + t]);
                acc.x += w * f.x;
                acc.y += w * f.y;
            }
        }
        for (; j < wn; j++) {
            float w = e_sh[j * H + hd];
            float2 f = __half22float2(feat2[(size_t)src_sh[j] * (HCv / 2) + t]);
            acc.x += w * f.x;
            acc.y += w * f.y;
        }
    }

    float inv = 1.f / d_run[hd];
    float v0 = acc.x * inv + bias[2 * t];
    float v1 = acc.y * inv + bias[2 * t + 1];
    if (apply_elu) {
        v0 = (v0 > 0.f) ? v0 : (__expf(v0) - 1.f);
        v1 = (v1 > 0.f) ? v1 : (__expf(v1) - 1.f);
    }
    if (F16OUT)
        *(__half2*)&outh[(size_t)n * HCv + 2 * t] = __floats2half2_rn(v0, v1);
    else
        *(float2*)&outf[(size_t)n * HCv + 2 * t] = make_float2(v0, v1);
}

// ---------------- launch ----------------
extern "C" void kernel_launch(void* const* d_in, const int* in_sizes, int n_in,
                              void* d_out, int out_size)
{
    const float* x   = (const float*)d_in[0];
    const int*   ei  = (const int*)d_in[1];
    const float* W1  = (const float*)d_in[2];
    const float* as1 = (const float*)d_in[3];
    const float* ad1 = (const float*)d_in[4];
    const float* b1  = (const float*)d_in[5];
    const float* W2  = (const float*)d_in[6];
    const float* as2 = (const float*)d_in[7];
    const float* ad2 = (const float*)d_in[8];
    const float* b2  = (const float*)d_in[9];
    const float* W3  = (const float*)d_in[10];
    const float* as3 = (const float*)d_in[11];
    const float* ad3 = (const float*)d_in[12];
    const float* b3  = (const float*)d_in[13];
    float* out = (float*)d_out;

    __half *x16, *w1, *w2, *w3, *h16, *o16;
    cudaGetSymbolAddress((void**)&x16, g_x16);
    cudaGetSymbolAddress((void**)&w1, g_w1);
    cudaGetSymbolAddress((void**)&w2, g_w2);
    cudaGetSymbolAddress((void**)&w3, g_w3);
    cudaGetSymbolAddress((void**)&h16, g_h16);
    cudaGetSymbolAddress((void**)&o16, g_o16);

    // --- prep + CSR build ---
    int prep_threads = NX4 + NW14 + NW24 + NW34;
    k_prep<<<(prep_threads + 255) / 256, 256>>>(x, W1, W2, W3);
    k_count<<<(ETOT + 255) / 256, 256>>>(ei);
    k_scan<<<1, 1024>>>();
    k_zero_cnt<<<(NN + 255) / 256, 256>>>();
    k_scatter<<<(ETOT + 255) / 256, 256>>>(ei);

    dim3 g12(4, (NN + 127) / 128);
    dim3 g3(1, (NN + 127) / 128);

    // --- layer 1 ---
    gemm_f16<<<g12, 256>>>(x16, w1, h16, NN, 512, 256);
    node_al<<<NN, 128>>>(h16, as1, ad1, 4, 128);
    gat_agg<4, 128, true><<<NN, 256>>>(h16, b1, nullptr, o16, 1);

    // --- layer 2 ---
    gemm_f16<<<g12, 256>>>(o16, w2, h16, NN, 512, 512);
    node_al<<<NN, 128>>>(h16, as2, ad2, 4, 128);
    gat_agg<4, 128, true><<<NN, 256>>>(h16, b2, nullptr, o16, 1);

    // --- layer 3 ---
    gemm_f16<<<g3, 256>>>(o16, w3, h16, NN, 64, 512);
    node_al<<<NN, 32>>>(h16, as3, ad3, 1, 64);
    gat_agg<1, 64, false><<<NN, 32>>>(h16, b3, out, nullptr, 0);
}

// round 15
// speedup vs baseline: 1.5190x; 1.0603x over previous
#include <cuda_runtime.h>
#include <cuda_fp16.h>
#include <math.h>

#define NN   10000
#define EIN  320000
#define ETOT 330000
#define MAXD 1024

// ---------------- device scratch ----------------
__device__ __half g_x16[NN * 256];
__device__ __half g_w1[256 * 512];
__device__ __half g_w2[512 * 512];
__device__ __half g_w3[512 * 64 + 256];
__device__ __half g_h16[NN * 512];
__device__ __half g_o16[NN * 512];
__device__ float  g_als[NN * 4];
__device__ float  g_ald[NN * 4];
__device__ int    g_rowptr[NN + 1];
__device__ int    g_cnt[NN];
__device__ int    g_epos[ETOT];
__device__ int    g_srcs[ETOT];

__device__ __forceinline__ int edge_src(const int* ei, int e) {
    return (e < EIN) ? ei[e] : (e - EIN);
}
__device__ __forceinline__ int edge_dst(const int* ei, int e) {
    return (e < EIN) ? ei[EIN + e] : (e - EIN);
}

// ---------------- fp16 conversions (GEMM-side prep) ----------------
__device__ __forceinline__ void cvt4(const float* in, __half* out, int i) {
    float4 v = *(const float4*)&in[i * 4];
    *(__half2*)&out[i * 4]     = __floats2half2_rn(v.x, v.y);
    *(__half2*)&out[i * 4 + 2] = __floats2half2_rn(v.z, v.w);
}

#define NX4  (NN * 256 / 4)
#define NW14 (256 * 512 / 4)
#define NW24 (512 * 512 / 4)
#define NW34 (512 * 64 / 4)

__global__ void k_conv(const float* __restrict__ x, const float* __restrict__ W1,
                       const float* __restrict__ W2, const float* __restrict__ W3)
{
    int i = blockIdx.x * blockDim.x + threadIdx.x;
    if (i < NX4) { cvt4(x, g_x16, i); return; }
    int j = i - NX4;
    if (j < NW14) { cvt4(W1, g_w1, j); return; }
    j -= NW14;
    if (j < NW24) { cvt4(W2, g_w2, j); return; }
    j -= NW24;
    if (j < NW34) { cvt4(W3, g_w3, j); return; }
}

// ---------------- CSR build (stream B) ----------------
__global__ void k_zero_cnt() {
    int i = blockIdx.x * blockDim.x + threadIdx.x;
    if (i < NN) g_cnt[i] = 0;
}

__global__ void k_count(const int* __restrict__ ei) {
    int e = blockIdx.x * blockDim.x + threadIdx.x;
    if (e < ETOT) g_epos[e] = atomicAdd(&g_cnt[edge_dst(ei, e)], 1);
}

__global__ void k_scan() {
    __shared__ int warp_sums[32];
    __shared__ int carry_sh;
    int t = threadIdx.x, lane = t & 31, w = t >> 5;
    if (t == 0) { carry_sh = 0; g_rowptr[0] = 0; }
    __syncthreads();
    for (int base = 0; base < NN; base += 1024) {
        int v = (base + t < NN) ? g_cnt[base + t] : 0;
        int s = v;
#pragma unroll
        for (int off = 1; off < 32; off <<= 1) {
            int x = __shfl_up_sync(0xffffffffu, s, off);
            if (lane >= off) s += x;
        }
        if (lane == 31) warp_sums[w] = s;
        __syncthreads();
        if (w == 0) {
            int ws = warp_sums[lane];
#pragma unroll
            for (int off = 1; off < 32; off <<= 1) {
                int x = __shfl_up_sync(0xffffffffu, ws, off);
                if (lane >= off) ws += x;
            }
            warp_sums[lane] = ws;
        }
        __syncthreads();
        int incl = s + ((w > 0) ? warp_sums[w - 1] : 0) + carry_sh;
        if (base + t < NN) g_rowptr[base + t + 1] = incl;
        __syncthreads();
        if (t == 1023) carry_sh = incl;
        __syncthreads();
    }
}

__global__ void k_scatter(const int* __restrict__ ei) {
    int e = blockIdx.x * blockDim.x + threadIdx.x;
    if (e < ETOT) {
        int d = edge_dst(ei, e);
        g_srcs[g_rowptr[d] + g_epos[e]] = edge_src(ei, e);
    }
}

// ---------------- cp.async helpers ----------------
#define CP16(smem_u32, gptr) \
    asm volatile("cp.async.cg.shared.global [%0], [%1], 16;" :: "r"(smem_u32), "l"(gptr))
#define CP_COMMIT() asm volatile("cp.async.commit_group;")

// ---------------- FP16 GEMM: 3-stage cp.async pipeline, ldmatrix(.trans) ----------------
__global__ __launch_bounds__(256) void gemm_f16(
    const __half* __restrict__ A, const __half* __restrict__ B,
    __half* __restrict__ C, int M, int N, int K)
{
    __shared__ __align__(16) __half As[3][128][40];
    __shared__ __align__(16) __half Bs[3][32][136];

    const int tid  = threadIdx.x;
    const int warp = tid >> 5, lane = tid & 31;
    const int warpM = warp >> 2, warpN = warp & 3;
    const int bm = blockIdx.y * 128, bn = blockIdx.x * 128;
    const int gid = lane >> 2, tig = lane & 3;

    float c[4][4][4];
#pragma unroll
    for (int mt = 0; mt < 4; mt++)
#pragma unroll
        for (int nt = 0; nt < 4; nt++)
#pragma unroll
            for (int r = 0; r < 4; r++) c[mt][nt][r] = 0.f;

    const int ntiles = K >> 5;
    const int ach0 = tid * 2, ach1 = tid * 2 + 1;

#define ISSUE_TILE(stage, k0)                                                     \
    {                                                                             \
        int _ar0 = ach0 >> 2, _ac0 = (ach0 & 3) * 8;                              \
        int _ar1 = ach1 >> 2, _ac1 = (ach1 & 3) * 8;                              \
        if (bm + _ar0 < M) {                                                      \
            unsigned _s = (unsigned)__cvta_generic_to_shared(&As[stage][_ar0][_ac0]); \
            CP16(_s, &A[(size_t)(bm + _ar0) * K + (k0) + _ac0]);                  \
        }                                                                         \
        if (bm + _ar1 < M) {                                                      \
            unsigned _s = (unsigned)__cvta_generic_to_shared(&As[stage][_ar1][_ac1]); \
            CP16(_s, &A[(size_t)(bm + _ar1) * K + (k0) + _ac1]);                  \
        }                                                                         \
        int _br0 = ach0 >> 4, _bc0 = (ach0 & 15) * 8;                             \
        int _br1 = ach1 >> 4, _bc1 = (ach1 & 15) * 8;                             \
        {                                                                         \
            unsigned _s = (unsigned)__cvta_generic_to_shared(&Bs[stage][_br0][_bc0]); \
            CP16(_s, &B[(size_t)((k0) + _br0) * N + bn + _bc0]);                  \
            _s = (unsigned)__cvta_generic_to_shared(&Bs[stage][_br1][_bc1]);      \
            CP16(_s, &B[(size_t)((k0) + _br1) * N + bn + _bc1]);                  \
        }                                                                         \
        CP_COMMIT();                                                              \
    }

    ISSUE_TILE(0, 0);
    if (ntiles > 1) ISSUE_TILE(1, 32);
    if (ntiles > 2) ISSUE_TILE(2, 64);

    for (int kt = 0; kt < ntiles; kt++) {
        if (kt + 2 < ntiles)
            asm volatile("cp.async.wait_group 2;");
        else if (kt + 1 < ntiles)
            asm volatile("cp.async.wait_group 1;");
        else
            asm volatile("cp.async.wait_group 0;");
        __syncthreads();

        const int s = kt % 3;
#pragma unroll
        for (int ks = 0; ks < 2; ks++) {
            const int kb = ks * 16;
            unsigned a[4][4], b[4][2];
#pragma unroll
            for (int mt = 0; mt < 4; mt++) {
                int m  = warpM * 64 + mt * 16 + (lane & 15);
                int kc = kb + 8 * (lane >> 4);
                unsigned addr = (unsigned)__cvta_generic_to_shared(&As[s][m][kc]);
                asm volatile(
                    "ldmatrix.sync.aligned.m8n8.x4.shared.b16 {%0,%1,%2,%3}, [%4];"
                    : "=r"(a[mt][0]), "=r"(a[mt][1]), "=r"(a[mt][2]), "=r"(a[mt][3])
                    : "r"(addr));
            }
#pragma unroll
            for (int np = 0; np < 2; np++) {
                int kr = kb + (lane & 15);
                int nc = warpN * 32 + np * 16 + 8 * (lane >> 4);
                unsigned addr = (unsigned)__cvta_generic_to_shared(&Bs[s][kr][nc]);
                unsigned r0, r1, r2, r3;
                asm volatile(
                    "ldmatrix.sync.aligned.m8n8.x4.trans.shared.b16 {%0,%1,%2,%3}, [%4];"
                    : "=r"(r0), "=r"(r1), "=r"(r2), "=r"(r3)
                    : "r"(addr));
                b[np * 2][0]     = r0;
                b[np * 2][1]     = r1;
                b[np * 2 + 1][0] = r2;
                b[np * 2 + 1][1] = r3;
            }
#pragma unroll
            for (int mt = 0; mt < 4; mt++)
#pragma unroll
                for (int nt = 0; nt < 4; nt++) {
                    asm volatile(
                        "mma.sync.aligned.m16n8k16.row.col.f32.f16.f16.f32 "
                        "{%0,%1,%2,%3}, {%4,%5,%6,%7}, {%8,%9}, {%0,%1,%2,%3};"
                        : "+f"(c[mt][nt][0]), "+f"(c[mt][nt][1]),
                          "+f"(c[mt][nt][2]), "+f"(c[mt][nt][3])
                        : "r"(a[mt][0]), "r"(a[mt][1]), "r"(a[mt][2]), "r"(a[mt][3]),
                          "r"(b[nt][0]), "r"(b[nt][1]));
                }
        }
        __syncthreads();
        if (kt + 3 < ntiles) ISSUE_TILE(kt % 3, (kt + 3) * 32);
    }

#pragma unroll
    for (int mt = 0; mt < 4; mt++) {
        int row0 = bm + warpM * 64 + mt * 16 + gid;
#pragma unroll
        for (int nt = 0; nt < 4; nt++) {
            int col = bn + warpN * 32 + nt * 8 + tig * 2;
            if (col < N) {
                if (row0 < M)
                    *(__half2*)&C[(size_t)row0 * N + col] =
                        __floats2half2_rn(c[mt][nt][0], c[mt][nt][1]);
                if (row0 + 8 < M)
                    *(__half2*)&C[(size_t)(row0 + 8) * N + col] =
                        __floats2half2_rn(c[mt][nt][2], c[mt][nt][3]);
            }
        }
    }
}

// ---------------- per-node attention logits ----------------
__global__ void node_al(const __half* __restrict__ feat,
                        const float* __restrict__ a_src,
                        const float* __restrict__ a_dst,
                        int Hn, int Cn)
{
    int n = blockIdx.x;
    int w = threadIdx.x >> 5;
    int lane = threadIdx.x & 31;
    if (w >= Hn) return;
    const __half* row = feat + (size_t)n * Hn * Cn + w * Cn;
    float s1 = 0.f, s2 = 0.f;
    for (int c = lane; c < Cn; c += 32) {
        float v = __half2float(row[c]);
        s1 += v * a_src[w * Cn + c];
        s2 += v * a_dst[w * Cn + c];
    }
#pragma unroll
    for (int off = 16; off; off >>= 1) {
        s1 += __shfl_xor_sync(0xffffffffu, s1, off);
        s2 += __shfl_xor_sync(0xffffffffu, s2, off);
    }
    if (lane == 0) {
        g_als[n * Hn + w] = s1;
        g_ald[n * Hn + w] = s2;
    }
}

// ---------------- fused softmax + aggregation ----------------
template <int H, int C, bool F16OUT>
__global__ void gat_agg(const __half* __restrict__ feat,
                        const float* __restrict__ bias,
                        float* __restrict__ outf,
                        __half* __restrict__ outh,
                        int apply_elu)
{
    constexpr int HCv = H * C;
    constexpr int BT = HCv / 2;
    int n = blockIdx.x;
    int t = threadIdx.x;
    int warp = t >> 5, lane = t & 31;

    int start = g_rowptr[n];
    int deg = g_rowptr[n + 1] - start;

    __shared__ float e_sh[MAXD * H];
    __shared__ int   src_sh[MAXD];
    __shared__ float m_run[H], d_run[H], f_sh[H];

    if (t < H) { m_run[t] = -1e30f; d_run[t] = 0.f; }

    float aldv[H];
#pragma unroll
    for (int hh = 0; hh < H; hh++) aldv[hh] = g_ald[n * H + hh];

    const int hd = (2 * t) / C;
    float2 acc = make_float2(0.f, 0.f);
    const __half2* feat2 = (const __half2*)feat;

    for (int w0 = 0; w0 < deg; w0 += MAXD) {
        int wn = min(MAXD, deg - w0);
        __syncthreads();

        for (int i = t; i < wn; i += BT) {
            int s = g_srcs[start + w0 + i];
            src_sh[i] = s;
            if (H == 4) {
                float4 av = *(const float4*)&g_als[s * 4];
                float e0 = av.x + aldv[0], e1 = av.y + aldv[1];
                float e2 = av.z + aldv[2], e3 = av.w + aldv[3];
                e_sh[i * 4 + 0] = (e0 > 0.f) ? e0 : 0.2f * e0;
                e_sh[i * 4 + 1] = (e1 > 0.f) ? e1 : 0.2f * e1;
                e_sh[i * 4 + 2] = (e2 > 0.f) ? e2 : 0.2f * e2;
                e_sh[i * 4 + 3] = (e3 > 0.f) ? e3 : 0.2f * e3;
            } else {
                float e0 = g_als[s] + aldv[0];
                e_sh[i] = (e0 > 0.f) ? e0 : 0.2f * e0;
            }
        }
        __syncthreads();

        if (warp < H) {
            float wm = -1e30f;
            for (int j = lane; j < wn; j += 32)
                wm = fmaxf(wm, e_sh[j * H + warp]);
#pragma unroll
            for (int off = 16; off; off >>= 1)
                wm = fmaxf(wm, __shfl_xor_sync(0xffffffffu, wm, off));
            float nm = fmaxf(m_run[warp], wm);
            float s = 0.f;
            for (int j = lane; j < wn; j += 32)
                s += __expf(e_sh[j * H + warp] - nm);
#pragma unroll
            for (int off = 16; off; off >>= 1)
                s += __shfl_xor_sync(0xffffffffu, s, off);
            if (lane == 0) {
                float f = __expf(m_run[warp] - nm);
                f_sh[warp] = f;
                d_run[warp] = d_run[warp] * f + s;
                m_run[warp] = nm;
            }
        }
        __syncthreads();

        for (int i = t; i < wn * H; i += BT) {
            int hh = i & (H - 1);
            e_sh[i] = __expf(e_sh[i] - m_run[hh]);
        }
        acc.x *= f_sh[hd];
        acc.y *= f_sh[hd];
        __syncthreads();

        int j = 0;
        for (; j + 4 <= wn; j += 4) {
#pragma unroll
            for (int u = 0; u < 4; u++) {
                float w = e_sh[(j + u) * H + hd];
                float2 f = __half22float2(feat2[(size_t)src_sh[j + u] * (HCv / 2) + t]);
                acc.x += w * f.x;
                acc.y += w * f.y;
            }
        }
        for (; j < wn; j++) {
            float w = e_sh[j * H + hd];
            float2 f = __half22float2(feat2[(size_t)src_sh[j] * (HCv / 2) + t]);
            acc.x += w * f.x;
            acc.y += w * f.y;
        }
    }

    float inv = 1.f / d_run[hd];
    float v0 = acc.x * inv + bias[2 * t];
    float v1 = acc.y * inv + bias[2 * t + 1];
    if (apply_elu) {
        v0 = (v0 > 0.f) ? v0 : (__expf(v0) - 1.f);
        v1 = (v1 > 0.f) ? v1 : (__expf(v1) - 1.f);
    }
    if (F16OUT)
        *(__half2*)&outh[(size_t)n * HCv + 2 * t] = __floats2half2_rn(v0, v1);
    else
        *(float2*)&outf[(size_t)n * HCv + 2 * t] = make_float2(v0, v1);
}

// ---------------- launch ----------------
extern "C" void kernel_launch(void* const* d_in, const int* in_sizes, int n_in,
                              void* d_out, int out_size)
{
    const float* x   = (const float*)d_in[0];
    const int*   ei  = (const int*)d_in[1];
    const float* W1  = (const float*)d_in[2];
    const float* as1 = (const float*)d_in[3];
    const float* ad1 = (const float*)d_in[4];
    const float* b1  = (const float*)d_in[5];
    const float* W2  = (const float*)d_in[6];
    const float* as2 = (const float*)d_in[7];
    const float* ad2 = (const float*)d_in[8];
    const float* b2  = (const float*)d_in[9];
    const float* W3  = (const float*)d_in[10];
    const float* as3 = (const float*)d_in[11];
    const float* ad3 = (const float*)d_in[12];
    const float* b3  = (const float*)d_in[13];
    float* out = (float*)d_out;

    __half *x16, *w1, *w2, *w3, *h16, *o16;
    cudaGetSymbolAddress((void**)&x16, g_x16);
    cudaGetSymbolAddress((void**)&w1, g_w1);
    cudaGetSymbolAddress((void**)&w2, g_w2);
    cudaGetSymbolAddress((void**)&w3, g_w3);
    cudaGetSymbolAddress((void**)&h16, g_h16);
    cudaGetSymbolAddress((void**)&o16, g_o16);

    // fork CSR build onto a side stream; it runs concurrently with
    // conversions + layer-1 GEMM + node_al, joining before gat_agg<1>.
    cudaStream_t sB;
    cudaEvent_t evFork, evJoin;
    cudaStreamCreateWithFlags(&sB, cudaStreamNonBlocking);
    cudaEventCreateWithFlags(&evFork, cudaEventDisableTiming);
    cudaEventCreateWithFlags(&evJoin, cudaEventDisableTiming);

    cudaEventRecord(evFork, 0);
    cudaStreamWaitEvent(sB, evFork, 0);

    // --- stream B: CSR build ---
    k_zero_cnt<<<(NN + 255) / 256, 256, 0, sB>>>();
    k_count<<<(ETOT + 255) / 256, 256, 0, sB>>>(ei);
    k_scan<<<1, 1024, 0, sB>>>();
    k_scatter<<<(ETOT + 255) / 256, 256, 0, sB>>>(ei);
    cudaEventRecord(evJoin, sB);

    // --- main stream: conversions + layer-1 GEMM chain ---
    int conv_threads = NX4 + NW14 + NW24 + NW34;
    k_conv<<<(conv_threads + 255) / 256, 256>>>(x, W1, W2, W3);

    dim3 g12(4, (NN + 127) / 128);
    dim3 g3(1, (NN + 127) / 128);

    gemm_f16<<<g12, 256>>>(x16, w1, h16, NN, 512, 256);
    node_al<<<NN, 128>>>(h16, as1, ad1, 4, 128);

    cudaStreamWaitEvent(0, evJoin, 0);   // CSR must be done before first agg
    gat_agg<4, 128, true><<<NN, 256>>>(h16, b1, nullptr, o16, 1);

    // --- layer 2 ---
    gemm_f16<<<g12, 256>>>(o16, w2, h16, NN, 512, 512);
    node_al<<<NN, 128>>>(h16, as2, ad2, 4, 128);
    gat_agg<4, 128, true><<<NN, 256>>>(h16, b2, nullptr, o16, 1);

    // --- layer 3 ---
    gemm_f16<<<g3, 256>>>(o16, w3, h16, NN, 64, 512);
    node_al<<<NN, 32>>>(h16, as3, ad3, 1, 64);
    gat_agg<1, 64, false><<<NN, 32>>>(h16, b3, out, nullptr, 0);
}

// round 16
// speedup vs baseline: 1.5653x; 1.0304x over previous
#include <cuda_runtime.h>
#include <cuda_fp16.h>
#include <math.h>

#define NN   10000
#define EIN  320000
#define ETOT 330000
#define MAXD 1024

// ---------------- device scratch ----------------
__device__ __half g_x16[NN * 256];
__device__ __half g_w1[256 * 512];
__device__ __half g_w2[512 * 512];
__device__ __half g_w3[512 * 64 + 256];
__device__ __half g_h16[NN * 512];
__device__ __half g_o16[NN * 512];
__device__ float  g_als[NN * 4];
__device__ float  g_ald[NN * 4];
__device__ int    g_rowptr[NN + 1];
__device__ int    g_cnt[NN];
__device__ int    g_epos[ETOT];
__device__ int    g_srcs[ETOT];

__device__ __forceinline__ int edge_src(const int* ei, int e) {
    return (e < EIN) ? ei[e] : (e - EIN);
}
__device__ __forceinline__ int edge_dst(const int* ei, int e) {
    return (e < EIN) ? ei[EIN + e] : (e - EIN);
}

// ---------------- fp16 conversions ----------------
__device__ __forceinline__ void cvt4(const float* in, __half* out, int i) {
    float4 v = *(const float4*)&in[i * 4];
    *(__half2*)&out[i * 4]     = __floats2half2_rn(v.x, v.y);
    *(__half2*)&out[i * 4 + 2] = __floats2half2_rn(v.z, v.w);
}

#define NX4  (NN * 256 / 4)
#define NW14 (256 * 512 / 4)
#define NW24 (512 * 512 / 4)
#define NW34 (512 * 64 / 4)

// x + W1 (needed before GEMM1) — main stream
__global__ void k_conv1(const float* __restrict__ x, const float* __restrict__ W1) {
    int i = blockIdx.x * blockDim.x + threadIdx.x;
    if (i < NX4) { cvt4(x, g_x16, i); return; }
    int j = i - NX4;
    if (j < NW14) cvt4(W1, g_w1, j);
}

// W2 + W3 — stream B (hidden under GEMM1)
__global__ void k_conv23(const float* __restrict__ W2, const float* __restrict__ W3) {
    int i = blockIdx.x * blockDim.x + threadIdx.x;
    if (i < NW24) { cvt4(W2, g_w2, i); return; }
    int j = i - NW24;
    if (j < NW34) cvt4(W3, g_w3, j);
}

// ---------------- CSR build (stream B) ----------------
__global__ void k_zero_cnt() {
    int i = blockIdx.x * blockDim.x + threadIdx.x;
    if (i < NN) g_cnt[i] = 0;
}

__global__ void k_count(const int* __restrict__ ei) {
    int e = blockIdx.x * blockDim.x + threadIdx.x;
    if (e < ETOT) g_epos[e] = atomicAdd(&g_cnt[edge_dst(ei, e)], 1);
}

__global__ void k_scan() {
    __shared__ int warp_sums[32];
    __shared__ int carry_sh;
    int t = threadIdx.x, lane = t & 31, w = t >> 5;
    if (t == 0) { carry_sh = 0; g_rowptr[0] = 0; }
    __syncthreads();
    for (int base = 0; base < NN; base += 1024) {
        int v = (base + t < NN) ? g_cnt[base + t] : 0;
        int s = v;
#pragma unroll
        for (int off = 1; off < 32; off <<= 1) {
            int x = __shfl_up_sync(0xffffffffu, s, off);
            if (lane >= off) s += x;
        }
        if (lane == 31) warp_sums[w] = s;
        __syncthreads();
        if (w == 0) {
            int ws = warp_sums[lane];
#pragma unroll
            for (int off = 1; off < 32; off <<= 1) {
                int x = __shfl_up_sync(0xffffffffu, ws, off);
                if (lane >= off) ws += x;
            }
            warp_sums[lane] = ws;
        }
        __syncthreads();
        int incl = s + ((w > 0) ? warp_sums[w - 1] : 0) + carry_sh;
        if (base + t < NN) g_rowptr[base + t + 1] = incl;
        __syncthreads();
        if (t == 1023) carry_sh = incl;
        __syncthreads();
    }
}

__global__ void k_scatter(const int* __restrict__ ei) {
    int e = blockIdx.x * blockDim.x + threadIdx.x;
    if (e < ETOT) {
        int d = edge_dst(ei, e);
        g_srcs[g_rowptr[d] + g_epos[e]] = edge_src(ei, e);
    }
}

// ---------------- cp.async helpers ----------------
#define CP16(smem_u32, gptr) \
    asm volatile("cp.async.cg.shared.global [%0], [%1], 16;" :: "r"(smem_u32), "l"(gptr))
#define CP_COMMIT() asm volatile("cp.async.commit_group;")

// ---------------- FP16 GEMM: K-tile 64, 3-stage cp.async, ldmatrix(.trans) ----------------
// dynamic smem: As[3][128][72] then Bs[3][64][136]
#define A_PITCH 72
#define B_PITCH 136
#define A_STAGE (128 * A_PITCH)          // halves per A stage
#define B_STAGE (64 * B_PITCH)           // halves per B stage
#define GEMM_SMEM ((3 * A_STAGE + 3 * B_STAGE) * 2)

__global__ __launch_bounds__(256) void gemm_f16(
    const __half* __restrict__ A, const __half* __restrict__ B,
    __half* __restrict__ C, int M, int N, int K)
{
    extern __shared__ __align__(16) __half sm[];
    __half* AsP = sm;
    __half* BsP = sm + 3 * A_STAGE;

    const int tid  = threadIdx.x;
    const int warp = tid >> 5, lane = tid & 31;
    const int warpM = warp >> 2, warpN = warp & 3;
    const int bm = blockIdx.y * 128, bn = blockIdx.x * 128;
    const int gid = lane >> 2, tig = lane & 3;

    float c[4][4][4];
#pragma unroll
    for (int mt = 0; mt < 4; mt++)
#pragma unroll
        for (int nt = 0; nt < 4; nt++)
#pragma unroll
            for (int r = 0; r < 4; r++) c[mt][nt][r] = 0.f;

    const int ntiles = K >> 6;

#define ISSUE_TILE(stage, kc)                                                     \
    {                                                                             \
        const int _k0 = (kc) << 6;                                                \
        _Pragma("unroll")                                                         \
        for (int _i = 0; _i < 4; _i++) {                                          \
            int _q = tid + 256 * _i;                                              \
            int _r = _q >> 3, _c = (_q & 7) * 8;                                  \
            if (bm + _r < M) {                                                    \
                unsigned _s = (unsigned)__cvta_generic_to_shared(                 \
                    &AsP[(stage) * A_STAGE + _r * A_PITCH + _c]);                 \
                CP16(_s, &A[(size_t)(bm + _r) * K + _k0 + _c]);                   \
            }                                                                     \
        }                                                                         \
        _Pragma("unroll")                                                         \
        for (int _i = 0; _i < 4; _i++) {                                          \
            int _q = tid + 256 * _i;                                              \
            int _r = _q >> 4, _c = (_q & 15) * 8;                                 \
            unsigned _s = (unsigned)__cvta_generic_to_shared(                     \
                &BsP[(stage) * B_STAGE + _r * B_PITCH + _c]);                     \
            CP16(_s, &B[(size_t)(_k0 + _r) * N + bn + _c]);                       \
        }                                                                         \
        CP_COMMIT();                                                              \
    }

    ISSUE_TILE(0, 0);
    if (ntiles > 1) ISSUE_TILE(1, 1);
    if (ntiles > 2) ISSUE_TILE(2, 2);

    for (int kt = 0; kt < ntiles; kt++) {
        if (kt + 2 < ntiles)
            asm volatile("cp.async.wait_group 2;");
        else if (kt + 1 < ntiles)
            asm volatile("cp.async.wait_group 1;");
        else
            asm volatile("cp.async.wait_group 0;");
        __syncthreads();

        const int s = kt % 3;
        const __half* Asb = &AsP[s * A_STAGE];
        const __half* Bsb = &BsP[s * B_STAGE];
#pragma unroll
        for (int ks = 0; ks < 4; ks++) {
            const int kb = ks * 16;
            unsigned a[4][4], b[4][2];
#pragma unroll
            for (int mt = 0; mt < 4; mt++) {
                int m  = warpM * 64 + mt * 16 + (lane & 15);
                int kc = kb + 8 * (lane >> 4);
                unsigned addr = (unsigned)__cvta_generic_to_shared(&Asb[m * A_PITCH + kc]);
                asm volatile(
                    "ldmatrix.sync.aligned.m8n8.x4.shared.b16 {%0,%1,%2,%3}, [%4];"
                    : "=r"(a[mt][0]), "=r"(a[mt][1]), "=r"(a[mt][2]), "=r"(a[mt][3])
                    : "r"(addr));
            }
#pragma unroll
            for (int np = 0; np < 2; np++) {
                int kr = kb + (lane & 15);
                int nc = warpN * 32 + np * 16 + 8 * (lane >> 4);
                unsigned addr = (unsigned)__cvta_generic_to_shared(&Bsb[kr * B_PITCH + nc]);
                unsigned r0, r1, r2, r3;
                asm volatile(
                    "ldmatrix.sync.aligned.m8n8.x4.trans.shared.b16 {%0,%1,%2,%3}, [%4];"
                    : "=r"(r0), "=r"(r1), "=r"(r2), "=r"(r3)
                    : "r"(addr));
                b[np * 2][0]     = r0;
                b[np * 2][1]     = r1;
                b[np * 2 + 1][0] = r2;
                b[np * 2 + 1][1] = r3;
            }
#pragma unroll
            for (int mt = 0; mt < 4; mt++)
#pragma unroll
                for (int nt = 0; nt < 4; nt++) {
                    asm volatile(
                        "mma.sync.aligned.m16n8k16.row.col.f32.f16.f16.f32 "
                        "{%0,%1,%2,%3}, {%4,%5,%6,%7}, {%8,%9}, {%0,%1,%2,%3};"
                        : "+f"(c[mt][nt][0]), "+f"(c[mt][nt][1]),
                          "+f"(c[mt][nt][2]), "+f"(c[mt][nt][3])
                        : "r"(a[mt][0]), "r"(a[mt][1]), "r"(a[mt][2]), "r"(a[mt][3]),
                          "r"(b[nt][0]), "r"(b[nt][1]));
                }
        }
        __syncthreads();
        if (kt + 3 < ntiles) ISSUE_TILE(kt % 3, kt + 3);
    }

#pragma unroll
    for (int mt = 0; mt < 4; mt++) {
        int row0 = bm + warpM * 64 + mt * 16 + gid;
#pragma unroll
        for (int nt = 0; nt < 4; nt++) {
            int col = bn + warpN * 32 + nt * 8 + tig * 2;
            if (col < N) {
                if (row0 < M)
                    *(__half2*)&C[(size_t)row0 * N + col] =
                        __floats2half2_rn(c[mt][nt][0], c[mt][nt][1]);
                if (row0 + 8 < M)
                    *(__half2*)&C[(size_t)(row0 + 8) * N + col] =
                        __floats2half2_rn(c[mt][nt][2], c[mt][nt][3]);
            }
        }
    }
}

// ---------------- per-node attention logits ----------------
__global__ void node_al(const __half* __restrict__ feat,
                        const float* __restrict__ a_src,
                        const float* __restrict__ a_dst,
                        int Hn, int Cn)
{
    int n = blockIdx.x;
    int w = threadIdx.x >> 5;
    int lane = threadIdx.x & 31;
    if (w >= Hn) return;
    const __half* row = feat + (size_t)n * Hn * Cn + w * Cn;
    float s1 = 0.f, s2 = 0.f;
    for (int c = lane; c < Cn; c += 32) {
        float v = __half2float(row[c]);
        s1 += v * a_src[w * Cn + c];
        s2 += v * a_dst[w * Cn + c];
    }
#pragma unroll
    for (int off = 16; off; off >>= 1) {
        s1 += __shfl_xor_sync(0xffffffffu, s1, off);
        s2 += __shfl_xor_sync(0xffffffffu, s2, off);
    }
    if (lane == 0) {
        g_als[n * Hn + w] = s1;
        g_ald[n * Hn + w] = s2;
    }
}

// ---------------- fused softmax + aggregation ----------------
template <int H, int C, bool F16OUT>
__global__ void gat_agg(const __half* __restrict__ feat,
                        const float* __restrict__ bias,
                        float* __restrict__ outf,
                        __half* __restrict__ outh,
                        int apply_elu)
{
    constexpr int HCv = H * C;
    constexpr int BT = HCv / 2;
    int n = blockIdx.x;
    int t = threadIdx.x;
    int warp = t >> 5, lane = t & 31;

    int start = g_rowptr[n];
    int deg = g_rowptr[n + 1] - start;

    __shared__ float e_sh[MAXD * H];
    __shared__ int   src_sh[MAXD];
    __shared__ float m_run[H], d_run[H], f_sh[H];

    if (t < H) { m_run[t] = -1e30f; d_run[t] = 0.f; }

    float aldv[H];
#pragma unroll
    for (int hh = 0; hh < H; hh++) aldv[hh] = g_ald[n * H + hh];

    const int hd = (2 * t) / C;
    float2 acc = make_float2(0.f, 0.f);
    const __half2* feat2 = (const __half2*)feat;

    for (int w0 = 0; w0 < deg; w0 += MAXD) {
        int wn = min(MAXD, deg - w0);
        __syncthreads();

        for (int i = t; i < wn; i += BT) {
            int s = g_srcs[start + w0 + i];
            src_sh[i] = s;
            if (H == 4) {
                float4 av = *(const float4*)&g_als[s * 4];
                float e0 = av.x + aldv[0], e1 = av.y + aldv[1];
                float e2 = av.z + aldv[2], e3 = av.w + aldv[3];
                e_sh[i * 4 + 0] = (e0 > 0.f) ? e0 : 0.2f * e0;
                e_sh[i * 4 + 1] = (e1 > 0.f) ? e1 : 0.2f * e1;
                e_sh[i * 4 + 2] = (e2 > 0.f) ? e2 : 0.2f * e2;
                e_sh[i * 4 + 3] = (e3 > 0.f) ? e3 : 0.2f * e3;
            } else {
                float e0 = g_als[s] + aldv[0];
                e_sh[i] = (e0 > 0.f) ? e0 : 0.2f * e0;
            }
        }
        __syncthreads();

        if (warp < H) {
            float wm = -1e30f;
            for (int j = lane; j < wn; j += 32)
                wm = fmaxf(wm, e_sh[j * H + warp]);
#pragma unroll
            for (int off = 16; off; off >>= 1)
                wm = fmaxf(wm, __shfl_xor_sync(0xffffffffu, wm, off));
            float nm = fmaxf(m_run[warp], wm);
            float s = 0.f;
            for (int j = lane; j < wn; j += 32)
                s += __expf(e_sh[j * H + warp] - nm);
#pragma unroll
            for (int off = 16; off; off >>= 1)
                s += __shfl_xor_sync(0xffffffffu, s, off);
            if (lane == 0) {
                float f = __expf(m_run[warp] - nm);
                f_sh[warp] = f;
                d_run[warp] = d_run[warp] * f + s;
                m_run[warp] = nm;
            }
        }
        __syncthreads();

        for (int i = t; i < wn * H; i += BT) {
            int hh = i & (H - 1);
            e_sh[i] = __expf(e_sh[i] - m_run[hh]);
        }
        acc.x *= f_sh[hd];
        acc.y *= f_sh[hd];
        __syncthreads();

        int j = 0;
        for (; j + 4 <= wn; j += 4) {
#pragma unroll
            for (int u = 0; u < 4; u++) {
                float w = e_sh[(j + u) * H + hd];
                float2 f = __half22float2(feat2[(size_t)src_sh[j + u] * (HCv / 2) + t]);
                acc.x += w * f.x;
                acc.y += w * f.y;
            }
        }
        for (; j < wn; j++) {
            float w = e_sh[j * H + hd];
            float2 f = __half22float2(feat2[(size_t)src_sh[j] * (HCv / 2) + t]);
            acc.x += w * f.x;
            acc.y += w * f.y;
        }
    }

    float inv = 1.f / d_run[hd];
    float v0 = acc.x * inv + bias[2 * t];
    float v1 = acc.y * inv + bias[2 * t + 1];
    if (apply_elu) {
        v0 = (v0 > 0.f) ? v0 : (__expf(v0) - 1.f);
        v1 = (v1 > 0.f) ? v1 : (__expf(v1) - 1.f);
    }
    if (F16OUT)
        *(__half2*)&outh[(size_t)n * HCv + 2 * t] = __floats2half2_rn(v0, v1);
    else
        *(float2*)&outf[(size_t)n * HCv + 2 * t] = make_float2(v0, v1);
}

// ---------------- launch ----------------
extern "C" void kernel_launch(void* const* d_in, const int* in_sizes, int n_in,
                              void* d_out, int out_size)
{
    const float* x   = (const float*)d_in[0];
    const int*   ei  = (const int*)d_in[1];
    const float* W1  = (const float*)d_in[2];
    const float* as1 = (const float*)d_in[3];
    const float* ad1 = (const float*)d_in[4];
    const float* b1  = (const float*)d_in[5];
    const float* W2  = (const float*)d_in[6];
    const float* as2 = (const float*)d_in[7];
    const float* ad2 = (const float*)d_in[8];
    const float* b2  = (const float*)d_in[9];
    const float* W3  = (const float*)d_in[10];
    const float* as3 = (const float*)d_in[11];
    const float* ad3 = (const float*)d_in[12];
    const float* b3  = (const float*)d_in[13];
    float* out = (float*)d_out;

    __half *x16, *w1, *w2, *w3, *h16, *o16;
    cudaGetSymbolAddress((void**)&x16, g_x16);
    cudaGetSymbolAddress((void**)&w1, g_w1);
    cudaGetSymbolAddress((void**)&w2, g_w2);
    cudaGetSymbolAddress((void**)&w3, g_w3);
    cudaGetSymbolAddress((void**)&h16, g_h16);
    cudaGetSymbolAddress((void**)&o16, g_o16);

    cudaFuncSetAttribute(gemm_f16, cudaFuncAttributeMaxDynamicSharedMemorySize, GEMM_SMEM);

    // fork side stream: W2/W3 conversion + CSR build, hidden under GEMM1.
    cudaStream_t sB;
    cudaEvent_t evFork, evJoin;
    cudaStreamCreateWithFlags(&sB, cudaStreamNonBlocking);
    cudaEventCreateWithFlags(&evFork, cudaEventDisableTiming);
    cudaEventCreateWithFlags(&evJoin, cudaEventDisableTiming);

    cudaEventRecord(evFork, 0);
    cudaStreamWaitEvent(sB, evFork, 0);

    // --- stream B: W2/W3 conv + CSR build ---
    k_conv23<<<(NW24 + NW34 + 255) / 256, 256, 0, sB>>>(W2, W3);
    k_zero_cnt<<<(NN + 255) / 256, 256, 0, sB>>>();
    k_count<<<(ETOT + 255) / 256, 256, 0, sB>>>(ei);
    k_scan<<<1, 1024, 0, sB>>>();
    k_scatter<<<(ETOT + 255) / 256, 256, 0, sB>>>(ei);
    cudaEventRecord(evJoin, sB);

    // --- main stream ---
    k_conv1<<<(NX4 + NW14 + 255) / 256, 256>>>(x, W1);

    dim3 g12(4, (NN + 127) / 128);
    dim3 g3(1, (NN + 127) / 128);

    gemm_f16<<<g12, 256, GEMM_SMEM>>>(x16, w1, h16, NN, 512, 256);
    node_al<<<NN, 128>>>(h16, as1, ad1, 4, 128);

    cudaStreamWaitEvent(0, evJoin, 0);
    gat_agg<4, 128, true><<<NN, 256>>>(h16, b1, nullptr, o16, 1);

    // --- layer 2 ---
    gemm_f16<<<g12, 256, GEMM_SMEM>>>(o16, w2, h16, NN, 512, 512);
    node_al<<<NN, 128>>>(h16, as2, ad2, 4, 128);
    gat_agg<4, 128, true><<<NN, 256>>>(h16, b2, nullptr, o16, 1);

    // --- layer 3 ---
    gemm_f16<<<g3, 256, GEMM_SMEM>>>(o16, w3, h16, NN, 64, 512);
    node_al<<<NN, 32>>>(h16, as3, ad3, 1, 64);
    gat_agg<1, 64, false><<<NN, 32>>>(h16, b3, out, nullptr, 0);
}